// round 7
// baseline (speedup 1.0000x reference)
#include <cuda_runtime.h>
#include <cstdint>
#include <math.h>

#define T_   384
#define B_   48
#define H_   256
#define G3   768
#define CSZ  8                 // CTAs per cluster
#define GB   3                 // batches per cluster
#define NCTA 128
#define THR  256               // 8 warps
#define NPASS 6

// ---------------- scratch ----------------
__device__ float g_gi[(size_t)T_ * B_ * G3];
__device__ float g_ys0[(size_t)T_ * B_ * H_];
__device__ float g_skipc[B_];
__device__ float g_dcar[B_];

// ---------------- helpers ----------------
__device__ __forceinline__ float sigm_fast(float x) {
    return __fdividef(1.f, 1.f + __expf(-x));
}
__device__ __forceinline__ float tanh_fast(float x) {
    return fmaf(2.f, sigm_fast(2.f * x), -1.f);
}

#define FMA4(acc, wv, hv) { acc = fmaf((wv).x,(hv).x,acc); acc = fmaf((wv).y,(hv).y,acc); \
                            acc = fmaf((wv).z,(hv).z,acc); acc = fmaf((wv).w,(hv).w,acc); }

__device__ __forceinline__ void advance_state(float& u, float& d, float& s, float dn) {
    float bup = rintf(u);
    float nu  = (s > 0.f) ? fminf(fmaxf(u + d, 0.f), 1.f) * (1.f - bup) : dn * bup;
    d = (s > 0.f) ? d : dn;
    s = ((ceilf(0.5f / nu) - 1.f) > 0.f) ? 1.f : 0.f;
    u = nu;
}

__device__ __forceinline__ unsigned smem_u32(const void* p) {
    unsigned a;
    asm("{ .reg .u64 t; cvta.to.shared.u64 t, %1; cvt.u32.u64 %0, t; }" : "=r"(a) : "l"(p));
    return a;
}
__device__ __forceinline__ unsigned mapa_u32(unsigned a, unsigned r) {
    unsigned o; asm("mapa.shared::cluster.u32 %0, %1, %2;" : "=r"(o) : "r"(a), "r"(r)); return o;
}
__device__ __forceinline__ void st_clu(unsigned a, float v) {
    asm volatile("st.shared::cluster.f32 [%0], %1;" :: "r"(a), "f"(v) : "memory");
}
__device__ __forceinline__ void mbar_init(unsigned a, unsigned cnt) {
    asm volatile("mbarrier.init.shared.b64 [%0], %1;" :: "r"(a), "r"(cnt) : "memory");
}
__device__ __forceinline__ void mbar_arrive_cluster(unsigned a) {
    asm volatile("mbarrier.arrive.release.cluster.shared::cluster.b64 _, [%0];"
                 :: "r"(a) : "memory");
}
__device__ __forceinline__ void mbar_wait(unsigned a, unsigned parity) {
    unsigned done;
    asm volatile("{\n\t.reg .pred p;\n\t"
                 "mbarrier.try_wait.parity.acquire.cluster.shared::cta.b64 p, [%1], %2, 0x989680;\n\t"
                 "selp.b32 %0, 1, 0, p;\n\t}"
                 : "=r"(done) : "r"(a), "r"(parity) : "memory");
    while (!done) {
        asm volatile("{\n\t.reg .pred p;\n\t"
                     "mbarrier.try_wait.parity.acquire.cluster.shared::cta.b64 p, [%1], %2, 0x989680;\n\t"
                     "selp.b32 %0, 1, 0, p;\n\t}"
                     : "=r"(done) : "r"(a), "r"(parity) : "memory");
    }
}
#define CLUSTER_SYNC() do { asm volatile("barrier.cluster.arrive.aligned;" ::: "memory"); \
                            asm volatile("barrier.cluster.wait.aligned;"   ::: "memory"); } while (0)

// ---------------- bulk gi GEMM (unchanged from R4) ----------------
__global__ void __launch_bounds__(128) gemm_xw(const float* __restrict__ x, int layer,
                                               const float* __restrict__ wih) {
    __shared__ float As[16][64];
    __shared__ float Bs[16][64];
    const float* A = layer ? (const float*)g_ys0 : x;
    const float* W = wih + (size_t)layer * G3 * H_;
    const int tid = threadIdx.x;
    const int m0 = blockIdx.x * 64, n0 = blockIdx.y * 64;
    const int tx = tid & 15, ty = tid >> 4;
    float acc[8][4];
#pragma unroll
    for (int i = 0; i < 8; i++)
#pragma unroll
        for (int j = 0; j < 4; j++) acc[i][j] = 0.f;

    for (int kt = 0; kt < 256; kt += 16) {
#pragma unroll
        for (int i = 0; i < 2; i++) {
            int idx = tid + i * 128;
            int row = idx >> 2, k4 = idx & 3;
            float4 a = *(const float4*)&A[(size_t)(m0 + row) * 256 + kt + k4 * 4];
            As[k4*4+0][row] = a.x; As[k4*4+1][row] = a.y;
            As[k4*4+2][row] = a.z; As[k4*4+3][row] = a.w;
            float4 b = *(const float4*)&W[(size_t)(n0 + row) * 256 + kt + k4 * 4];
            Bs[k4*4+0][row] = b.x; Bs[k4*4+1][row] = b.y;
            Bs[k4*4+2][row] = b.z; Bs[k4*4+3][row] = b.w;
        }
        __syncthreads();
#pragma unroll
        for (int kk = 0; kk < 16; kk++) {
            float4 b4 = *(const float4*)&Bs[kk][tx * 4];
            float4 a0 = *(const float4*)&As[kk][ty * 8];
            float4 a1 = *(const float4*)&As[kk][ty * 8 + 4];
            float am[8] = {a0.x, a0.y, a0.z, a0.w, a1.x, a1.y, a1.z, a1.w};
            float bm[4] = {b4.x, b4.y, b4.z, b4.w};
#pragma unroll
            for (int i = 0; i < 8; i++)
#pragma unroll
                for (int j = 0; j < 4; j++)
                    acc[i][j] = fmaf(am[i], bm[j], acc[i][j]);
        }
        __syncthreads();
    }
#pragma unroll
    for (int i = 0; i < 8; i++) {
        float4 o = make_float4(acc[i][0], acc[i][1], acc[i][2], acc[i][3]);
        *(float4*)&g_gi[(size_t)(m0 + ty * 8 + i) * G3 + n0 + tx * 4] = o;
    }
}

// ---------------- clustered recurrence, warp-autonomous steps ----------------
__global__ void __launch_bounds__(THR, 1) __cluster_dims__(CSZ, 1, 1)
rec_kernel(int layer,
           const float* __restrict__ hiddens,
           const float* __restrict__ whh,
           const float* __restrict__ bih,
           const float* __restrict__ bhh,
           const float* __restrict__ lw,
           const float* __restrict__ lb,
           float* __restrict__ d_out)
{
    __shared__ float h_s[2][GB][H_];        // double-buffered h by step parity
    __shared__ float parts_s[2][GB][64];    // double-buffered skip partials [b][rk*8+w]
    __shared__ unsigned long long mbar;

    const int tid  = threadIdx.x;
    const int w    = tid >> 5;
    const int lane = tid & 31;
    unsigned rk; asm("mov.u32 %0, %%cluster_ctarank;" : "=r"(rk));
    const int cid = blockIdx.x / CSZ;
    const int bg0 = cid * GB;

    float* ys      = layer ? d_out : g_ys0;
    float* hs_out  = d_out + (size_t)T_ * B_ * H_ + (size_t)layer * B_ * H_;
    float* tu_out  = d_out + (size_t)T_ * B_ * H_ + 2 * B_ * H_;   // [B][2T]
    const float* gi  = g_gi;
    const float* h0  = hiddens + (size_t)layer * H_;
    const float* wh  = whh + (size_t)layer * G3 * H_;
    const float* bi  = bih + (size_t)layer * G3;
    const float* bh  = bhh + (size_t)layer * G3;
    const float* lwp = lw + (size_t)layer * H_;

    // ---- w_hh in registers: pass p -> gate p>>1, unit w*4 + (p&1)*2 + r2 ----
    const int r2 = lane >> 4, k16 = lane & 15;
    float4 wv[NPASS][4];
    const float4* whp = (const float4*)wh;
#pragma unroll
    for (int p = 0; p < NPASS; p++) {
        int row = (p >> 1) * 256 + (int)rk * 32 + w * 4 + (p & 1) * 2 + r2;
#pragma unroll
        for (int i = 0; i < 4; i++) wv[p][i] = whp[(size_t)row * 64 + k16 * 4 + i];
    }

    // ---- epilogue lane mapping: half-lane el<6 handles (b=el>>1, usub=(el&1)*2+r2) ----
    const int el = lane & 15;
    const bool eact = (el < 6);
    const int b    = (el >> 1) < GB ? (el >> 1) : GB - 1;
    const int pl   = el & 1;
    const int usub = pl * 2 + r2;
    const int egu  = (int)rk * 32 + w * 4 + usub;
    const float bir = bi[egu], biz = bi[256 + egu], bin = bi[512 + egu];
    const float bhr = bh[egu], bhz = bh[256 + egu], bhn = bh[512 + egu];
    const float lwj = lwp[egu];

    // ---- skip-state lanes (12..14), redundant in every warp ----
    const bool skl = (lane >= 12 && lane < 12 + GB);
    const int  sb  = skl ? lane - 12 : 0;
    float su = 1.f, sd = 0.f, ss = 0.f, lb_ = 0.f;
    if (skl) {
        lb_ = lb[layer];
        if (layer) { sd = g_dcar[bg0 + sb]; ss = g_skipc[bg0 + sb]; }
    }

    // ---- DSMEM peer bases ----
    unsigned hb = smem_u32(h_s), pb = smem_u32(parts_s), mb = smem_u32(&mbar);
    unsigned peer_h[CSZ], peer_p[CSZ], peer_m[CSZ];
#pragma unroll
    for (int r = 0; r < CSZ; r++) {
        peer_h[r] = mapa_u32(hb, r); peer_p[r] = mapa_u32(pb, r); peer_m[r] = mapa_u32(mb, r);
    }

    if (tid == 0) mbar_init(mb, 8 * CSZ);   // 64 arrivals per phase
    for (int i = tid; i < GB * H_; i += THR)
        (&h_s[0][0][0])[i] = h0[i & (H_ - 1)];
    __syncthreads();
    CLUSTER_SYNC();

    // gi prefetch for t=0
    float gir = 0.f, giz = 0.f, gin = 0.f;
    if (eact) {
        const float* gp = gi + ((size_t)bg0 + b) * G3 + egu;
        gir = gp[0]; giz = gp[256]; gin = gp[512];
    }

    for (int t = 0; t < T_; t++) {
        if (t > 0) mbar_wait(mb, (unsigned)((t - 1) & 1));
        const int rb = t & 1, wbuf = rb ^ 1;

        // ---- skip-state (lanes 12..14, deterministic fixed-order sum) ----
        float bu_bc = 0.f, sk_bc = 0.f;
        if (skl) {
            if (t > 0) {
                const float4* pp = (const float4*)&parts_s[rb][sb][0];
                float4 s4 = make_float4(0.f, 0.f, 0.f, 0.f);
#pragma unroll
                for (int c = 0; c < 16; c++) {
                    float4 v = pp[c];
                    s4.x += v.x; s4.y += v.y; s4.z += v.z; s4.w += v.w;
                }
                float ps = (s4.x + s4.y) + (s4.z + s4.w);
                advance_state(su, sd, ss, sigm_fast(ps + lb_));
            }
            bu_bc = rintf(su); sk_bc = ss;
            if (w == 0 && rk == 0)
                tu_out[(size_t)(bg0 + sb) * (2 * T_) + layer * T_ + t] = bu_bc;
        }

        // ---- GEMV: h from read buffer, butterfly leaves sums in all lanes of each half ----
        float4 hreg[GB][4];
#pragma unroll
        for (int bb = 0; bb < GB; bb++)
#pragma unroll
            for (int i = 0; i < 4; i++)
                hreg[bb][i] = *(const float4*)&h_s[rb][bb][k16 * 16 + i * 4];

        float a[NPASS][GB];
#pragma unroll
        for (int p = 0; p < NPASS; p++) {
            float a0 = 0.f, a1 = 0.f, a2 = 0.f;
#pragma unroll
            for (int i = 0; i < 4; i++) {
                FMA4(a0, wv[p][i], hreg[0][i]);
                FMA4(a1, wv[p][i], hreg[1][i]);
                FMA4(a2, wv[p][i], hreg[2][i]);
            }
#pragma unroll
            for (int m = 8; m >= 1; m >>= 1) {
                a0 += __shfl_xor_sync(0xffffffffu, a0, m);
                a1 += __shfl_xor_sync(0xffffffffu, a1, m);
                a2 += __shfl_xor_sync(0xffffffffu, a2, m);
            }
            a[p][0] = a0; a[p][1] = a1; a[p][2] = a2;
        }

        // ---- warp-local epilogue ----
        float bu = __shfl_sync(0xffffffffu, bu_bc, 12 + b);
        float sk = __shfl_sync(0xffffffffu, sk_bc, 12 + b);
        float pd = 0.f;
        if (eact) {
#define PK(arr) ((b == 0) ? (arr)[0] : ((b == 1) ? (arr)[1] : (arr)[2]))
            float ghr = pl ? PK(a[1]) : PK(a[0]);
            float ghz = pl ? PK(a[3]) : PK(a[2]);
            float ghn = pl ? PK(a[5]) : PK(a[4]);
#undef PK
            float hprev = h_s[rb][b][egu];
            float r = sigm_fast(gir + bir + ghr + bhr);
            float z = sigm_fast(giz + biz + ghz + bhz);
            float n = tanh_fast(gin + bin + r * (ghn + bhn));
            float cand = (1.f - z) * n + z * hprev;
            float hns = cand * bu;
            float nh = (sk > 0.f) ? hprev * (1.f - bu) : hns;
            unsigned off = (unsigned)((wbuf * GB + b) * H_ + egu) * 4u;
#pragma unroll
            for (int r8 = 0; r8 < CSZ; r8++) st_clu(peer_h[r8] + off, nh);
            ys[((size_t)t * B_ + bg0 + b) * H_ + egu] = nh;
            if (t == T_ - 1) hs_out[(size_t)(bg0 + b) * H_ + egu] = nh;
            pd = hns * lwj;
        }
        pd += __shfl_xor_sync(0xffffffffu, pd, 1);
        pd += __shfl_xor_sync(0xffffffffu, pd, 16);
        if (eact && pl == 0 && r2 == 0) {   // lanes 0,2,4: one per batch
            unsigned poff = (unsigned)((wbuf * GB + b) * 64 + (int)rk * 8 + w) * 4u;
#pragma unroll
            for (int r8 = 0; r8 < CSZ; r8++) st_clu(peer_p[r8] + poff, pd);
        }
        if (eact && t + 1 < T_) {
            const float* gp = gi + ((size_t)(t + 1) * B_ + bg0 + b) * G3 + egu;
            gir = gp[0]; giz = gp[256]; gin = gp[512];
        }
        __syncwarp();
        if (lane == 31) {
#pragma unroll
            for (int r8 = 0; r8 < CSZ; r8++) mbar_arrive_cluster(peer_m[r8]);
        }
    }

    // layer-0 final carry
    mbar_wait(mb, (unsigned)((T_ - 1) & 1));
    if (layer == 0 && w == 0 && rk == 0 && skl) {
        const float4* pp = (const float4*)&parts_s[0][sb][0];   // t=383 wrote buffer 0
        float4 s4 = make_float4(0.f, 0.f, 0.f, 0.f);
#pragma unroll
        for (int c = 0; c < 16; c++) {
            float4 v = pp[c];
            s4.x += v.x; s4.y += v.y; s4.z += v.z; s4.w += v.w;
        }
        float ps = (s4.x + s4.y) + (s4.z + s4.w);
        advance_state(su, sd, ss, sigm_fast(ps + lb_));
        g_dcar[bg0 + sb] = sd; g_skipc[bg0 + sb] = ss;
    }
    CLUSTER_SYNC();   // no CTA exits while peers may still remote-store
}

// ---------------- launcher ----------------
extern "C" void kernel_launch(void* const* d_in, const int* in_sizes, int n_in,
                              void* d_out, int out_size) {
    const float* x   = (const float*)d_in[0];
    const float* hid = (const float*)d_in[1];
    const float* wih = (const float*)d_in[2];
    const float* whh = (const float*)d_in[3];
    const float* bih = (const float*)d_in[4];
    const float* bhh = (const float*)d_in[5];
    const float* lw  = (const float*)d_in[6];
    const float* lb  = (const float*)d_in[7];
    float* out = (float*)d_out;

    dim3 ggrid(T_ * B_ / 64, G3 / 64);   // (288, 12)
    gemm_xw<<<ggrid, 128>>>(x, 0, wih);
    rec_kernel<<<NCTA, THR>>>(0, hid, whh, bih, bhh, lw, lb, out);
    gemm_xw<<<ggrid, 128>>>(x, 1, wih);
    rec_kernel<<<NCTA, THR>>>(1, hid, whh, bih, bhh, lw, lb, out);
}

// round 8
// speedup vs baseline: 1.3048x; 1.3048x over previous
#include <cuda_runtime.h>
#include <cstdint>
#include <math.h>

#define T_   384
#define B_   48
#define H_   256
#define G3   768
#define CSZ  8                 // CTAs per cluster
#define GB   3                 // batches per cluster
#define NCTA 128
#define THR  256               // 8 warps
#define NPASS 6

// ---------------- scratch ----------------
__device__ float g_gi[(size_t)T_ * B_ * G3];
__device__ float g_ys0[(size_t)T_ * B_ * H_];
__device__ float g_skipc[B_];
__device__ float g_dcar[B_];

// ---------------- helpers ----------------
__device__ __forceinline__ float sigm_fast(float x) {
    return __fdividef(1.f, 1.f + __expf(-x));
}
__device__ __forceinline__ float tanh_fast(float x) {
    return fmaf(2.f, sigm_fast(2.f * x), -1.f);
}

#define FMA4(acc, wv, hv) { acc = fmaf((wv).x,(hv).x,acc); acc = fmaf((wv).y,(hv).y,acc); \
                            acc = fmaf((wv).z,(hv).z,acc); acc = fmaf((wv).w,(hv).w,acc); }

__device__ __forceinline__ void advance_state(float& u, float& d, float& s, float dn) {
    float bup = rintf(u);
    float nu  = (s > 0.f) ? fminf(fmaxf(u + d, 0.f), 1.f) * (1.f - bup) : dn * bup;
    d = (s > 0.f) ? d : dn;
    s = ((ceilf(0.5f / nu) - 1.f) > 0.f) ? 1.f : 0.f;
    u = nu;
}

__device__ __forceinline__ unsigned smem_u32(const void* p) {
    unsigned a;
    asm("{ .reg .u64 t; cvta.to.shared.u64 t, %1; cvt.u32.u64 %0, t; }" : "=r"(a) : "l"(p));
    return a;
}
__device__ __forceinline__ unsigned mapa_u32(unsigned a, unsigned r) {
    unsigned o; asm("mapa.shared::cluster.u32 %0, %1, %2;" : "=r"(o) : "r"(a), "r"(r)); return o;
}
__device__ __forceinline__ void st_clu4(unsigned a, float x, float y, float z, float w) {
    asm volatile("st.shared::cluster.v4.f32 [%0], {%1, %2, %3, %4};"
                 :: "r"(a), "f"(x), "f"(y), "f"(z), "f"(w) : "memory");
}
#define CLUSTER_SYNC() do { asm volatile("barrier.cluster.arrive.aligned;" ::: "memory"); \
                            asm volatile("barrier.cluster.wait.aligned;"   ::: "memory"); } while (0)

// ---------------- bulk gi GEMM (unchanged from R4) ----------------
__global__ void __launch_bounds__(128) gemm_xw(const float* __restrict__ x, int layer,
                                               const float* __restrict__ wih) {
    __shared__ float As[16][64];
    __shared__ float Bs[16][64];
    const float* A = layer ? (const float*)g_ys0 : x;
    const float* W = wih + (size_t)layer * G3 * H_;
    const int tid = threadIdx.x;
    const int m0 = blockIdx.x * 64, n0 = blockIdx.y * 64;
    const int tx = tid & 15, ty = tid >> 4;
    float acc[8][4];
#pragma unroll
    for (int i = 0; i < 8; i++)
#pragma unroll
        for (int j = 0; j < 4; j++) acc[i][j] = 0.f;

    for (int kt = 0; kt < 256; kt += 16) {
#pragma unroll
        for (int i = 0; i < 2; i++) {
            int idx = tid + i * 128;
            int row = idx >> 2, k4 = idx & 3;
            float4 a = *(const float4*)&A[(size_t)(m0 + row) * 256 + kt + k4 * 4];
            As[k4*4+0][row] = a.x; As[k4*4+1][row] = a.y;
            As[k4*4+2][row] = a.z; As[k4*4+3][row] = a.w;
            float4 b = *(const float4*)&W[(size_t)(n0 + row) * 256 + kt + k4 * 4];
            Bs[k4*4+0][row] = b.x; Bs[k4*4+1][row] = b.y;
            Bs[k4*4+2][row] = b.z; Bs[k4*4+3][row] = b.w;
        }
        __syncthreads();
#pragma unroll
        for (int kk = 0; kk < 16; kk++) {
            float4 b4 = *(const float4*)&Bs[kk][tx * 4];
            float4 a0 = *(const float4*)&As[kk][ty * 8];
            float4 a1 = *(const float4*)&As[kk][ty * 8 + 4];
            float am[8] = {a0.x, a0.y, a0.z, a0.w, a1.x, a1.y, a1.z, a1.w};
            float bm[4] = {b4.x, b4.y, b4.z, b4.w};
#pragma unroll
            for (int i = 0; i < 8; i++)
#pragma unroll
                for (int j = 0; j < 4; j++)
                    acc[i][j] = fmaf(am[i], bm[j], acc[i][j]);
        }
        __syncthreads();
    }
#pragma unroll
    for (int i = 0; i < 8; i++) {
        float4 o = make_float4(acc[i][0], acc[i][1], acc[i][2], acc[i][3]);
        *(float4*)&g_gi[(size_t)(m0 + ty * 8 + i) * G3 + n0 + tx * 4] = o;
    }
}

// ---------------- clustered recurrence: warp-local epilogue, 1 sync/step ----------------
__global__ void __launch_bounds__(THR, 1) __cluster_dims__(CSZ, 1, 1)
rec_kernel(int layer,
           const float* __restrict__ hiddens,
           const float* __restrict__ whh,
           const float* __restrict__ bih,
           const float* __restrict__ bhh,
           const float* __restrict__ lw,
           const float* __restrict__ lb,
           float* __restrict__ d_out)
{
    __shared__ __align__(16) float  h_s[2][GB][H_];   // double-buffered by parity
    __shared__ __align__(16) float4 parts_s[2][64];   // [rk*8 + w] -> (b0,b1,b2,_)

    const int tid  = threadIdx.x;
    const int w    = tid >> 5;
    const int lane = tid & 31;
    unsigned rk; asm("mov.u32 %0, %%cluster_ctarank;" : "=r"(rk));
    const int cid = blockIdx.x / CSZ;
    const int bg0 = cid * GB;

    float* ys      = layer ? d_out : g_ys0;
    float* hs_out  = d_out + (size_t)T_ * B_ * H_ + (size_t)layer * B_ * H_;
    float* tu_out  = d_out + (size_t)T_ * B_ * H_ + 2 * B_ * H_;   // [B][2T]
    const float* gi  = g_gi;
    const float* h0  = hiddens + (size_t)layer * H_;
    const float* wh  = whh + (size_t)layer * G3 * H_;
    const float* bi  = bih + (size_t)layer * G3;
    const float* bh  = bhh + (size_t)layer * G3;
    const float* lwp = lw + (size_t)layer * H_;

    // ---- w_hh in regs: pass p -> gate p>>1, unit w*4 + (p&1)*2 + r2 ----
    const int r2 = lane >> 4, k16 = lane & 15;
    float4 wv[NPASS][4];
    const float4* whp = (const float4*)wh;
#pragma unroll
    for (int p = 0; p < NPASS; p++) {
        int row = (p >> 1) * 256 + (int)rk * 32 + w * 4 + (p & 1) * 2 + r2;
#pragma unroll
        for (int i = 0; i < 4; i++) wv[p][i] = whp[(size_t)row * 64 + k16 * 4 + i];
    }

    // ---- cell mapping: el<6 -> (batch=el>>1, pl=el&1, usub=pl*2+r2) ----
    const int el   = lane & 15;
    const bool eact = (el < 6);
    const int b    = eact ? (el >> 1) : 0;
    const int pl   = el & 1;
    const int usub = pl * 2 + r2;
    const int egu  = (int)rk * 32 + w * 4 + usub;
    const bool vlane = eact && (pl == 0) && (r2 == 0);   // lanes 0,2,4: own units w*4..w*4+3 of batch b
    const float bir = bi[egu], biz = bi[256 + egu], bin = bi[512 + egu];
    const float bhr = bh[egu], bhz = bh[256 + egu], bhn = bh[512 + egu];
    const float lwj = lwp[egu];

    // ---- skip-state lanes 12..14, redundant in every warp (deterministic) ----
    const bool skl = (lane >= 12 && lane < 12 + GB);
    const int  sb  = skl ? lane - 12 : 0;
    float su = 1.f, sd = 0.f, ss = 0.f, lb_ = 0.f;
    if (skl) {
        lb_ = lb[layer];
        if (layer) { sd = g_dcar[bg0 + sb]; ss = g_skipc[bg0 + sb]; }
    }

    // ---- DSMEM peer bases ----
    unsigned hb = smem_u32(h_s), pb = smem_u32(parts_s);
    unsigned peer_h[CSZ], peer_p[CSZ];
#pragma unroll
    for (int r = 0; r < CSZ; r++) { peer_h[r] = mapa_u32(hb, r); peer_p[r] = mapa_u32(pb, r); }

    for (int i = tid; i < GB * H_; i += THR)
        (&h_s[0][0][0])[i] = h0[i & (H_ - 1)];
    __syncthreads();
    CLUSTER_SYNC();

    // gi prefetch for t=0
    float gir = 0.f, giz = 0.f, gin = 0.f;
    if (eact) {
        const float* gp = gi + ((size_t)bg0 + b) * G3 + egu;
        gir = gp[0]; giz = gp[256]; gin = gp[512];
    }

    for (int t = 0; t < T_; t++) {
        const int rb = t & 1, wb2 = rb ^ 1;

        // ---- skip-state (fixed-order componentwise sum -> deterministic) ----
        float bu_bc = 0.f, sk_bc = 0.f;
        if (skl) {
            if (t > 0) {
                const float4* pp = &parts_s[rb][0];
                float4 s4 = make_float4(0.f, 0.f, 0.f, 0.f);
#pragma unroll
                for (int c = 0; c < 64; c++) {
                    float4 v = pp[c];
                    s4.x += v.x; s4.y += v.y; s4.z += v.z;
                }
                float ps = (sb == 0) ? s4.x : ((sb == 1) ? s4.y : s4.z);
                advance_state(su, sd, ss, sigm_fast(ps + lb_));
            }
            bu_bc = rintf(su); sk_bc = ss;
            if (w == 0 && rk == 0)
                tu_out[(size_t)(bg0 + sb) * (2 * T_) + layer * T_ + t] = bu_bc;
        }

        // ---- GEMV (reductions leave sums in every lane of each half) ----
        float4 hreg[GB][4];
#pragma unroll
        for (int bb = 0; bb < GB; bb++)
#pragma unroll
            for (int i = 0; i < 4; i++)
                hreg[bb][i] = *(const float4*)&h_s[rb][bb][k16 * 16 + i * 4];

        float a[NPASS][GB];
#pragma unroll
        for (int p = 0; p < NPASS; p++) {
            float a0 = 0.f, a1 = 0.f, a2 = 0.f;
#pragma unroll
            for (int i = 0; i < 4; i++) {
                FMA4(a0, wv[p][i], hreg[0][i]);
                FMA4(a1, wv[p][i], hreg[1][i]);
                FMA4(a2, wv[p][i], hreg[2][i]);
            }
#pragma unroll
            for (int m = 8; m >= 1; m >>= 1) {
                a0 += __shfl_xor_sync(0xffffffffu, a0, m);
                a1 += __shfl_xor_sync(0xffffffffu, a1, m);
                a2 += __shfl_xor_sync(0xffffffffu, a2, m);
            }
            a[p][0] = a0; a[p][1] = a1; a[p][2] = a2;
        }

        // ---- warp-local epilogue ----
        float bu = __shfl_sync(0xffffffffu, bu_bc, 12 + b);
        float sk = __shfl_sync(0xffffffffu, sk_bc, 12 + b);
        float nh = 0.f, pd = 0.f;
        if (eact) {
#define PK(arr) ((b == 0) ? (arr)[0] : ((b == 1) ? (arr)[1] : (arr)[2]))
            float ghr = pl ? PK(a[1]) : PK(a[0]);
            float ghz = pl ? PK(a[3]) : PK(a[2]);
            float ghn = pl ? PK(a[5]) : PK(a[4]);
#undef PK
            float hprev = h_s[rb][b][egu];
            float r = sigm_fast(gir + bir + ghr + bhr);
            float z = sigm_fast(giz + biz + ghz + bhz);
            float n = tanh_fast(gin + bin + r * (ghn + bhn));
            float cand = (1.f - z) * n + z * hprev;
            float hns = cand * bu;
            nh = (sk > 0.f) ? hprev * (1.f - bu) : hns;
            pd = hns * lwj;
        }
        // gather 4 consecutive units (usub 0..3) into the usub0 lane: one v4 store
        float vy = __shfl_xor_sync(0xffffffffu, nh, 16);   // usub1
        float vz = __shfl_xor_sync(0xffffffffu, nh, 1);    // usub2
        float vw = __shfl_xor_sync(0xffffffffu, nh, 17);   // usub3
        if (vlane) {
            unsigned off = (unsigned)((wb2 * GB + b) * H_ + egu) * 4u;
#pragma unroll
            for (int r8 = 0; r8 < CSZ; r8++) st_clu4(peer_h[r8] + off, nh, vy, vz, vw);
            float4 o = make_float4(nh, vy, vz, vw);
            *(float4*)&ys[((size_t)t * B_ + bg0 + b) * H_ + egu] = o;
            if (t == T_ - 1) *(float4*)&hs_out[(size_t)(bg0 + b) * H_ + egu] = o;
        }
        // skip-gate partial: sum over this warp's 4 units per batch, pack 3 batches
        pd += __shfl_xor_sync(0xffffffffu, pd, 1);
        pd += __shfl_xor_sync(0xffffffffu, pd, 16);
        float p1 = __shfl_sync(0xffffffffu, pd, 2);
        float p2 = __shfl_sync(0xffffffffu, pd, 4);
        if (lane == 0) {
            unsigned poff = (unsigned)(wb2 * 64 + (int)rk * 8 + w) * 16u;
#pragma unroll
            for (int r8 = 0; r8 < CSZ; r8++) st_clu4(peer_p[r8] + poff, pd, p1, p2, 0.f);
        }
        // prefetch gi for t+1 (hides under the barrier)
        if (eact && t + 1 < T_) {
            const float* gp = gi + ((size_t)(t + 1) * B_ + bg0 + b) * G3 + egu;
            gir = gp[0]; giz = gp[256]; gin = gp[512];
        }
        CLUSTER_SYNC();
    }

    // layer-0 final carry (t=383 wrote parts buffer 0; guarded by loop-end sync)
    if (layer == 0 && w == 0 && rk == 0 && skl) {
        const float4* pp = &parts_s[0][0];
        float4 s4 = make_float4(0.f, 0.f, 0.f, 0.f);
#pragma unroll
        for (int c = 0; c < 64; c++) {
            float4 v = pp[c];
            s4.x += v.x; s4.y += v.y; s4.z += v.z;
        }
        float ps = (sb == 0) ? s4.x : ((sb == 1) ? s4.y : s4.z);
        advance_state(su, sd, ss, sigm_fast(ps + lb_));
        g_dcar[bg0 + sb] = sd; g_skipc[bg0 + sb] = ss;
    }
    CLUSTER_SYNC();
}

// ---------------- launcher ----------------
extern "C" void kernel_launch(void* const* d_in, const int* in_sizes, int n_in,
                              void* d_out, int out_size) {
    const float* x   = (const float*)d_in[0];
    const float* hid = (const float*)d_in[1];
    const float* wih = (const float*)d_in[2];
    const float* whh = (const float*)d_in[3];
    const float* bih = (const float*)d_in[4];
    const float* bhh = (const float*)d_in[5];
    const float* lw  = (const float*)d_in[6];
    const float* lb  = (const float*)d_in[7];
    float* out = (float*)d_out;

    dim3 ggrid(T_ * B_ / 64, G3 / 64);   // (288, 12)
    gemm_xw<<<ggrid, 128>>>(x, 0, wih);
    rec_kernel<<<NCTA, THR>>>(0, hid, whh, bih, bhh, lw, lb, out);
    gemm_xw<<<ggrid, 128>>>(x, 1, wih);
    rec_kernel<<<NCTA, THR>>>(1, hid, whh, bih, bhh, lw, lb, out);
}

// round 9
// speedup vs baseline: 2.3968x; 1.8369x over previous
#include <cuda_runtime.h>
#include <cstdint>
#include <math.h>

#define T_   384
#define B_   48
#define H_   256
#define G3   768
#define CSZ  8                 // CTAs per cluster
#define GB   3                 // batches per cluster
#define NCTA 128
#define THR  256               // 8 warps
#define NPASS 6
#define HROW 52                // padded words per k16-row (conflict-free)

// ---------------- scratch ----------------
__device__ float g_gi[(size_t)T_ * B_ * G3];
__device__ float g_ys0[(size_t)T_ * B_ * H_];
__device__ float g_skipc[B_];
__device__ float g_dcar[B_];

// ---------------- helpers ----------------
__device__ __forceinline__ float sigm_fast(float x) {
    return __fdividef(1.f, 1.f + __expf(-x));
}
__device__ __forceinline__ float tanh_fast(float x) {
    return fmaf(2.f, sigm_fast(2.f * x), -1.f);
}

#define FMA4(acc, wv, hv) { acc = fmaf((wv).x,(hv).x,acc); acc = fmaf((wv).y,(hv).y,acc); \
                            acc = fmaf((wv).z,(hv).z,acc); acc = fmaf((wv).w,(hv).w,acc); }

__device__ __forceinline__ void advance_state(float& u, float& d, float& s, float dn) {
    float bup = rintf(u);
    float nu  = (s > 0.f) ? fminf(fmaxf(u + d, 0.f), 1.f) * (1.f - bup) : dn * bup;
    d = (s > 0.f) ? d : dn;
    s = ((ceilf(0.5f / nu) - 1.f) > 0.f) ? 1.f : 0.f;
    u = nu;
}

__device__ __forceinline__ unsigned smem_u32(const void* p) {
    unsigned a;
    asm("{ .reg .u64 t; cvta.to.shared.u64 t, %1; cvt.u32.u64 %0, t; }" : "=r"(a) : "l"(p));
    return a;
}
__device__ __forceinline__ unsigned mapa_u32(unsigned a, unsigned r) {
    unsigned o; asm("mapa.shared::cluster.u32 %0, %1, %2;" : "=r"(o) : "r"(a), "r"(r)); return o;
}
__device__ __forceinline__ void st_clu(unsigned a, float v) {
    asm volatile("st.shared::cluster.f32 [%0], %1;" :: "r"(a), "f"(v) : "memory");
}
#define CLUSTER_SYNC() do { asm volatile("barrier.cluster.arrive.aligned;" ::: "memory"); \
                            asm volatile("barrier.cluster.wait.aligned;"   ::: "memory"); } while (0)

// ---------------- bulk gi GEMM (unchanged from R4) ----------------
__global__ void __launch_bounds__(128) gemm_xw(const float* __restrict__ x, int layer,
                                               const float* __restrict__ wih) {
    __shared__ float As[16][64];
    __shared__ float Bs[16][64];
    const float* A = layer ? (const float*)g_ys0 : x;
    const float* W = wih + (size_t)layer * G3 * H_;
    const int tid = threadIdx.x;
    const int m0 = blockIdx.x * 64, n0 = blockIdx.y * 64;
    const int tx = tid & 15, ty = tid >> 4;
    float acc[8][4];
#pragma unroll
    for (int i = 0; i < 8; i++)
#pragma unroll
        for (int j = 0; j < 4; j++) acc[i][j] = 0.f;

    for (int kt = 0; kt < 256; kt += 16) {
#pragma unroll
        for (int i = 0; i < 2; i++) {
            int idx = tid + i * 128;
            int row = idx >> 2, k4 = idx & 3;
            float4 a = *(const float4*)&A[(size_t)(m0 + row) * 256 + kt + k4 * 4];
            As[k4*4+0][row] = a.x; As[k4*4+1][row] = a.y;
            As[k4*4+2][row] = a.z; As[k4*4+3][row] = a.w;
            float4 b = *(const float4*)&W[(size_t)(n0 + row) * 256 + kt + k4 * 4];
            Bs[k4*4+0][row] = b.x; Bs[k4*4+1][row] = b.y;
            Bs[k4*4+2][row] = b.z; Bs[k4*4+3][row] = b.w;
        }
        __syncthreads();
#pragma unroll
        for (int kk = 0; kk < 16; kk++) {
            float4 b4 = *(const float4*)&Bs[kk][tx * 4];
            float4 a0 = *(const float4*)&As[kk][ty * 8];
            float4 a1 = *(const float4*)&As[kk][ty * 8 + 4];
            float am[8] = {a0.x, a0.y, a0.z, a0.w, a1.x, a1.y, a1.z, a1.w};
            float bm[4] = {b4.x, b4.y, b4.z, b4.w};
#pragma unroll
            for (int i = 0; i < 8; i++)
#pragma unroll
                for (int j = 0; j < 4; j++)
                    acc[i][j] = fmaf(am[i], bm[j], acc[i][j]);
        }
        __syncthreads();
    }
#pragma unroll
    for (int i = 0; i < 8; i++) {
        float4 o = make_float4(acc[i][0], acc[i][1], acc[i][2], acc[i][3]);
        *(float4*)&g_gi[(size_t)(m0 + ty * 8 + i) * G3 + n0 + tx * 4] = o;
    }
}

// h address helper: unit j (0..255), batch b -> padded smem word index
#define HIDX(j, b) (((j) >> 4) * HROW + (b) * 16 + ((j) & 15))

// ---------------- clustered recurrence (R4 structure, padded h + fast math) ----------------
__global__ void __launch_bounds__(THR, 1) __cluster_dims__(CSZ, 1, 1)
rec_kernel(int layer,
           const float* __restrict__ hiddens,
           const float* __restrict__ whh,
           const float* __restrict__ bih,
           const float* __restrict__ bhh,
           const float* __restrict__ lw,
           const float* __restrict__ lb,
           float* __restrict__ d_out)
{
    __shared__ __align__(16) float h_p[16 * HROW];   // padded h: row=k16, word=b*16+(j&15)
    __shared__ float gh_s[32][3][GB];
    __shared__ float parts_s[CSZ][GB];
    __shared__ float s_bu[GB], s_sk[GB];

    const int tid  = threadIdx.x;
    const int w    = tid >> 5;
    const int lane = tid & 31;
    unsigned rk; asm("mov.u32 %0, %%cluster_ctarank;" : "=r"(rk));
    const int cid = blockIdx.x / CSZ;
    const int bg0 = cid * GB;

    float* ys      = layer ? d_out : g_ys0;
    float* hs_out  = d_out + (size_t)T_ * B_ * H_ + (size_t)layer * B_ * H_;
    float* tu_out  = d_out + (size_t)T_ * B_ * H_ + 2 * B_ * H_;   // [B][2T]
    const float* gi  = g_gi;
    const float* h0  = hiddens + (size_t)layer * H_;
    const float* wh  = whh + (size_t)layer * G3 * H_;
    const float* bi  = bih + (size_t)layer * G3;
    const float* bh  = bhh + (size_t)layer * G3;
    const float* lwp = lw + (size_t)layer * H_;

    // ---- w_hh slices in registers ----
    const int r2 = lane >> 4, k16 = lane & 15;
    float4 wv[NPASS][4];
    const float4* whp = (const float4*)wh;
#pragma unroll
    for (int p = 0; p < NPASS; p++) {
        int row = (p >> 1) * 256 + (int)rk * 32 + w * 4 + (p & 1) * 2 + r2;
#pragma unroll
        for (int i = 0; i < 4; i++) wv[p][i] = whp[(size_t)row * 64 + k16 * 4 + i];
    }
    // epilogue constants (warps 0-2: lane -> (batch=w, unit=lane))
    const int eb = w, eu = lane, egu = (int)rk * 32 + eu;
    float bir = 0, biz = 0, bin = 0, bhr = 0, bhz = 0, bhn = 0, lwj = 0;
    if (w < 3) {
        bir = bi[egu]; biz = bi[256 + egu]; bin = bi[512 + egu];
        bhr = bh[egu]; bhz = bh[256 + egu]; bhn = bh[512 + egu];
        lwj = lwp[egu];
    }
    // skip-state (warp 3, lanes<GB; redundant per CTA, deterministic)
    float su = 1.f, sd = 0.f, ss = 0.f, lb_ = 0.f;
    if (w == 3 && lane < GB) {
        lb_ = lb[layer];
        if (layer) { sd = g_dcar[bg0 + lane]; ss = g_skipc[bg0 + lane]; }
    }
    // DSMEM peer addresses
    unsigned hb = smem_u32(h_p), pb = smem_u32(parts_s);
    unsigned peer_h[CSZ], peer_p[CSZ];
#pragma unroll
    for (int r = 0; r < CSZ; r++) { peer_h[r] = mapa_u32(hb, r); peer_p[r] = mapa_u32(pb, r); }

    // init h (each CTA holds full h for its 3 batches, padded layout)
    for (int i = tid; i < GB * H_; i += THR) {
        int b = i >> 8, j = i & 255;
        h_p[HIDX(j, b)] = h0[j];
    }
    __syncthreads();
    CLUSTER_SYNC();

    for (int t = 0; t < T_; t++) {
        // gi prefetch for this step's epilogue (hidden under GEMV)
        float gir = 0.f, giz = 0.f, gin = 0.f;
        if (w < 3) {
            const float* gp = gi + ((size_t)t * B_ + bg0 + eb) * G3 + egu;
            gir = gp[0]; giz = gp[256]; gin = gp[512];
        }
        // skip-state update from step t-1 partials
        if (w == 3 && lane < GB) {
            if (t > 0) {
                float ps = 0.f;
#pragma unroll
                for (int r = 0; r < CSZ; r++) ps += parts_s[r][lane];
                advance_state(su, sd, ss, sigm_fast(ps + lb_));
            }
            float bu = rintf(su);
            s_bu[lane] = bu; s_sk[lane] = ss;
            if (rk == 0) tu_out[(size_t)(bg0 + lane) * (2 * T_) + layer * T_ + t] = bu;
        }
        // load this lane's h k-slice (conflict-free padded rows)
        float4 hreg[GB][4];
#pragma unroll
        for (int b = 0; b < GB; b++)
#pragma unroll
            for (int i = 0; i < 4; i++)
                hreg[b][i] = *(const float4*)&h_p[k16 * HROW + b * 16 + i * 4];
        // GEMV: NPASS passes, each = 1 gate-row per lane-half x 3 batches
#pragma unroll
        for (int p = 0; p < NPASS; p++) {
            float a0 = 0.f, a1 = 0.f, a2 = 0.f;
#pragma unroll
            for (int i = 0; i < 4; i++) {
                FMA4(a0, wv[p][i], hreg[0][i]);
                FMA4(a1, wv[p][i], hreg[1][i]);
                FMA4(a2, wv[p][i], hreg[2][i]);
            }
#pragma unroll
            for (int m = 8; m >= 1; m >>= 1) {
                a0 += __shfl_xor_sync(0xffffffffu, a0, m);
                a1 += __shfl_xor_sync(0xffffffffu, a1, m);
                a2 += __shfl_xor_sync(0xffffffffu, a2, m);
            }
            if (k16 == 0) {
                int u = w * 4 + (p & 1) * 2 + r2, g = p >> 1;
                gh_s[u][g][0] = a0; gh_s[u][g][1] = a1; gh_s[u][g][2] = a2;
            }
        }
        __syncthreads();   // gh_s, s_bu, s_sk ready

        if (w < 3) {
            float ghr = gh_s[eu][0][eb], ghz = gh_s[eu][1][eb], ghn = gh_s[eu][2][eb];
            float bu = s_bu[eb], sk = s_sk[eb];
            float hprev = h_p[HIDX(egu, eb)];
            float r = sigm_fast(gir + bir + ghr + bhr);
            float z = sigm_fast(giz + biz + ghz + bhz);
            float n = tanh_fast(gin + bin + r * (ghn + bhn));
            float cand = (1.f - z) * n + z * hprev;
            float hns = cand * bu;
            float nh = (sk > 0.f) ? hprev * (1.f - bu) : hns;
            h_p[HIDX(egu, eb)] = nh;
            unsigned off = (unsigned)HIDX(egu, eb) * 4u;
#pragma unroll
            for (int r7 = 0; r7 < CSZ; r7++)
                if (r7 != (int)rk) st_clu(peer_h[r7] + off, nh);
            ys[((size_t)t * B_ + bg0 + eb) * H_ + egu] = nh;
            if (t == T_ - 1) hs_out[(size_t)(bg0 + eb) * H_ + egu] = nh;
            float pd = hns * lwj;
#pragma unroll
            for (int m = 16; m >= 1; m >>= 1) pd += __shfl_xor_sync(0xffffffffu, pd, m);
            if (lane == 0) {
                parts_s[rk][eb] = pd;
                unsigned poff = (unsigned)((int)rk * GB + eb) * 4u;
#pragma unroll
                for (int r7 = 0; r7 < CSZ; r7++)
                    if (r7 != (int)rk) st_clu(peer_p[r7] + poff, pd);
            }
        }
        CLUSTER_SYNC();    // publish h slices + partials cluster-wide
    }

    // layer-0 final carry (skip, d) for layer 1
    if (layer == 0 && w == 3 && lane < GB && rk == 0) {
        float ps = 0.f;
#pragma unroll
        for (int r = 0; r < CSZ; r++) ps += parts_s[r][lane];
        advance_state(su, sd, ss, sigm_fast(ps + lb_));
        g_dcar[bg0 + lane] = sd; g_skipc[bg0 + lane] = ss;
    }
}

// ---------------- launcher ----------------
extern "C" void kernel_launch(void* const* d_in, const int* in_sizes, int n_in,
                              void* d_out, int out_size) {
    const float* x   = (const float*)d_in[0];
    const float* hid = (const float*)d_in[1];
    const float* wih = (const float*)d_in[2];
    const float* whh = (const float*)d_in[3];
    const float* bih = (const float*)d_in[4];
    const float* bhh = (const float*)d_in[5];
    const float* lw  = (const float*)d_in[6];
    const float* lb  = (const float*)d_in[7];
    float* out = (float*)d_out;

    dim3 ggrid(T_ * B_ / 64, G3 / 64);   // (288, 12)
    gemm_xw<<<ggrid, 128>>>(x, 0, wih);
    rec_kernel<<<NCTA, THR>>>(0, hid, whh, bih, bhh, lw, lb, out);
    gemm_xw<<<ggrid, 128>>>(x, 1, wih);
    rec_kernel<<<NCTA, THR>>>(1, hid, whh, bih, bhh, lw, lb, out);
}